// round 13
// baseline (speedup 1.0000x reference)
#include <cuda_runtime.h>
#include <math.h>
#include <stdint.h>

#define D      512
#define B      256
#define FOURD  2048
#define QS     1024   // 2*D
#define SPLITS 8
#define NW     8      // warps per attn block (256 threads)

// tensor-core GEMM tiling
#define GBM 64
#define GBN 64
#define GBK 16
#define GNIT (QS / GBK)   // 64

// ---- scratch (no allocations allowed) ----
__device__ float g_Wcomb[FOURD * QS];   // [2048][1024] row-major: col<512 -> W_ih+W_hh, else W_ih
__device__ float g_bsum[FOURD];
__device__ float g_qstar[B * QS];       // [h | r] row-major
__device__ float g_c[B * D];
__device__ float g_gates[B * FOURD];
__device__ int   g_segoff[B + 1];
// split-attention partials
__device__ float g_pm[B * SPLITS];
__device__ float g_pd[B * SPLITS];
__device__ float g_pr[B * SPLITS * D];

__device__ __forceinline__ float sigf(float v) { return 1.0f / (1.0f + expf(-v)); }

__device__ __forceinline__ void cp_async16(uint32_t dst_smem, const void* src) {
    asm volatile("cp.async.cg.shared.global [%0], [%1], 16;" :: "r"(dst_smem), "l"(src));
}

__device__ __forceinline__ uint32_t f2tf32(float x) {
    uint32_t r; asm("cvt.rna.tf32.f32 %0, %1;" : "=r"(r) : "f"(x)); return r;
}

__device__ __forceinline__ void mma_tf32(float* c, const uint32_t* a, const uint32_t* b) {
    asm volatile(
        "mma.sync.aligned.m16n8k8.row.col.f32.tf32.tf32.f32 "
        "{%0,%1,%2,%3}, {%4,%5,%6,%7}, {%8,%9}, {%0,%1,%2,%3};\n"
        : "+f"(c[0]), "+f"(c[1]), "+f"(c[2]), "+f"(c[3])
        : "r"(a[0]), "r"(a[1]), "r"(a[2]), "r"(a[3]), "r"(b[0]), "r"(b[1]));
}

// ---------------- fused init: Wcomb + bsum + step0 + segscan ----------------
#define WCOMB_BLKS (FOURD * QS / 4 / 256)   // 2048
#define STEP0_BLKS (B * D / 256)            // 512
__global__ void k_init(const void* __restrict__ raw, int N,
                       const float* __restrict__ W_ih, const float* __restrict__ W_hh,
                       const float* __restrict__ b_ih, const float* __restrict__ b_hh) {
    int blk = blockIdx.x;
    int t = threadIdx.x;
    if (blk < WCOMB_BLKS) {
        int i4 = blk * 256 + t;
        float4 v = ((const float4*)W_ih)[i4];
        int idx = i4 * 4;
        int k = idx & (QS - 1);
        int n = idx >> 10;
        if (k < D) {
            float4 w = *(const float4*)(W_hh + n * D + k);
            v.x += w.x; v.y += w.y; v.z += w.z; v.w += w.w;
        }
        ((float4*)g_Wcomb)[i4] = v;
        if (i4 < FOURD) g_bsum[i4] = b_ih[i4] + b_hh[i4];
    } else if (blk < WCOMB_BLKS + STEP0_BLKS) {
        int idx = (blk - WCOMB_BLKS) * 256 + t;
        int j = idx & (D - 1);
        float gi = b_ih[j]         + b_hh[j];
        float gg = b_ih[2 * D + j] + b_hh[2 * D + j];
        float go = b_ih[3 * D + j] + b_hh[3 * D + j];
        float c  = sigf(gi) * tanhf(gg);
        float h  = sigf(go) * tanhf(c);
        int b = idx >> 9;
        g_c[idx] = c;
        g_qstar[b * QS + j] = h;
    } else {
        const int* p32 = (const int*)raw;
        bool is64 = (p32[N - 1] == 0) || (p32[N - 2] == 0);
        int i = (blk - WCOMB_BLKS - STEP0_BLKS) * 256 + t;
        if (i >= N) return;
        int cur = is64 ? (int)((const long long*)raw)[i] : p32[i];
        if (i == 0) {
            for (int j = 0; j <= cur; j++) g_segoff[j] = 0;
        } else {
            int prev = is64 ? (int)((const long long*)raw)[i - 1] : p32[i - 1];
            for (int j = prev + 1; j <= cur; j++) g_segoff[j] = i;
        }
        if (i == N - 1) {
            for (int j = cur + 1; j <= B; j++) g_segoff[j] = N;
        }
    }
}

// ---------------- LSTM elementwise, float4, 128-thr blocks (single gates buffer) ----------------
__global__ void __launch_bounds__(128) k_lstm_ew() {
    int idx = blockIdx.x * 128 + threadIdx.x;   // over B*D/4
    if (idx >= B * D / 4) return;
    int b = idx >> 7;
    int j = (idx & 127) * 4;
    const float* g = &g_gates[(size_t)b * FOURD];
    float4 gi = *(const float4*)&g[j];
    float4 gf = *(const float4*)&g[D + j];
    float4 gg = *(const float4*)&g[2 * D + j];
    float4 go = *(const float4*)&g[3 * D + j];
    float4 bi = *(const float4*)&g_bsum[j];
    float4 bf = *(const float4*)&g_bsum[D + j];
    float4 bg = *(const float4*)&g_bsum[2 * D + j];
    float4 bo = *(const float4*)&g_bsum[3 * D + j];
    gi.x += bi.x; gi.y += bi.y; gi.z += bi.z; gi.w += bi.w;
    gf.x += bf.x; gf.y += bf.y; gf.z += bf.z; gf.w += bf.w;
    gg.x += bg.x; gg.y += bg.y; gg.z += bg.z; gg.w += bg.w;
    go.x += bo.x; go.y += bo.y; go.z += bo.z; go.w += bo.w;
    float4 cold = *(const float4*)&g_c[b * D + j];
    float4 cnew, hnew;
    cnew.x = sigf(gf.x) * cold.x + sigf(gi.x) * tanhf(gg.x);
    cnew.y = sigf(gf.y) * cold.y + sigf(gi.y) * tanhf(gg.y);
    cnew.z = sigf(gf.z) * cold.z + sigf(gi.z) * tanhf(gg.z);
    cnew.w = sigf(gf.w) * cold.w + sigf(gi.w) * tanhf(gg.w);
    hnew.x = sigf(go.x) * tanhf(cnew.x);
    hnew.y = sigf(go.y) * tanhf(cnew.y);
    hnew.z = sigf(go.z) * tanhf(cnew.z);
    hnew.w = sigf(go.w) * tanhf(cnew.w);
    *(float4*)&g_c[b * D + j] = cnew;
    *(float4*)&g_qstar[b * QS + j] = hnew;
}

// ---------------- gates GEMM v5: 3xTF32 tensor cores, 64x64 tile, full K ----------------
// C[m][n] = sum_k qstar[m][k] * Wcomb[n][k]  (written raw; bias added in lstm_ew)
__global__ void __launch_bounds__(256) k_gemm_tc() {
    __shared__ __align__(16) float As[3][GBM][GBK + 4];   // 3*64*20*4 = 15360B
    __shared__ __align__(16) float Bs[3][GBN][GBK + 4];   // 15360B
    int n0 = blockIdx.x * GBN, m0 = blockIdx.y * GBM;
    int t = threadIdx.x;
    int lane = t & 31, wid = t >> 5;
    int warp_m = wid >> 2, warp_n = wid & 3;    // 2 x 4 warp grid
    int g = lane >> 2, tig = lane & 3;

    float acc[2][2][4];
    #pragma unroll
    for (int i = 0; i < 2; i++)
        #pragma unroll
        for (int j = 0; j < 2; j++)
            #pragma unroll
            for (int kq = 0; kq < 4; kq++) acc[i][j][kq] = 0.0f;

    // copy slot: one 16B chunk per thread per matrix per stage (64 rows x 4 chunks = 256)
    int crow = t >> 2;
    int ckq  = (t & 3) * 4;

    const float* srcA = g_qstar + (size_t)(m0 + crow) * QS + ckq;
    const float* srcB = g_Wcomb + (size_t)(n0 + crow) * QS + ckq;

    // prologue: stages 0,1
    #pragma unroll
    for (int s = 0; s < 2; s++) {
        cp_async16(__cvta_generic_to_shared(&As[s][crow][ckq]), srcA + s * GBK);
        cp_async16(__cvta_generic_to_shared(&Bs[s][crow][ckq]), srcB + s * GBK);
        asm volatile("cp.async.commit_group;");
    }

    for (int it = 0; it < GNIT; it++) {
        if (it < GNIT - 1) asm volatile("cp.async.wait_group 1;");
        else               asm volatile("cp.async.wait_group 0;");
        __syncthreads();
        if (it + 2 < GNIT) {
            int st = (it + 2) % 3;
            cp_async16(__cvta_generic_to_shared(&As[st][crow][ckq]), srcA + (it + 2) * GBK);
            cp_async16(__cvta_generic_to_shared(&Bs[st][crow][ckq]), srcB + (it + 2) * GBK);
            asm volatile("cp.async.commit_group;");
        }
        int cb = it % 3;
        #pragma unroll
        for (int ks = 0; ks < 2; ks++) {
            int kb = ks * 8;
            // load + split A fragments (2 m16 tiles)
            uint32_t ah[2][4], al[2][4];
            #pragma unroll
            for (int mt = 0; mt < 2; mt++) {
                int mb = warp_m * 32 + mt * 16;
                float f0 = As[cb][mb + g    ][kb + tig    ];
                float f1 = As[cb][mb + g + 8][kb + tig    ];
                float f2 = As[cb][mb + g    ][kb + tig + 4];
                float f3 = As[cb][mb + g + 8][kb + tig + 4];
                ah[mt][0] = f2tf32(f0); al[mt][0] = f2tf32(f0 - __uint_as_float(ah[mt][0]));
                ah[mt][1] = f2tf32(f1); al[mt][1] = f2tf32(f1 - __uint_as_float(ah[mt][1]));
                ah[mt][2] = f2tf32(f2); al[mt][2] = f2tf32(f2 - __uint_as_float(ah[mt][2]));
                ah[mt][3] = f2tf32(f3); al[mt][3] = f2tf32(f3 - __uint_as_float(ah[mt][3]));
            }
            // load + split B fragments (2 n8 tiles)
            uint32_t bh[2][2], bl[2][2];
            #pragma unroll
            for (int nt = 0; nt < 2; nt++) {
                int nb = warp_n * 16 + nt * 8;
                float f0 = Bs[cb][nb + g][kb + tig    ];
                float f1 = Bs[cb][nb + g][kb + tig + 4];
                bh[nt][0] = f2tf32(f0); bl[nt][0] = f2tf32(f0 - __uint_as_float(bh[nt][0]));
                bh[nt][1] = f2tf32(f1); bl[nt][1] = f2tf32(f1 - __uint_as_float(bh[nt][1]));
            }
            #pragma unroll
            for (int mt = 0; mt < 2; mt++)
                #pragma unroll
                for (int nt = 0; nt < 2; nt++) {
                    mma_tf32(acc[mt][nt], ah[mt], bh[nt]);
                    mma_tf32(acc[mt][nt], ah[mt], bl[nt]);
                    mma_tf32(acc[mt][nt], al[mt], bh[nt]);
                }
        }
    }

    // epilogue: scatter fragments
    #pragma unroll
    for (int mt = 0; mt < 2; mt++) {
        #pragma unroll
        for (int nt = 0; nt < 2; nt++) {
            int row0 = m0 + warp_m * 32 + mt * 16 + g;
            int col  = n0 + warp_n * 16 + nt * 8 + 2 * tig;
            *(float2*)&g_gates[(size_t)row0 * FOURD + col] =
                make_float2(acc[mt][nt][0], acc[mt][nt][1]);
            *(float2*)&g_gates[(size_t)(row0 + 8) * FOURD + col] =
                make_float2(acc[mt][nt][2], acc[mt][nt][3]);
        }
    }
}

// ---------------- split segment attention (round-9 proven shape) ----------------
__global__ void __launch_bounds__(256) k_attn_part(const float* __restrict__ x) {
    __shared__ __align__(16) float q_sh[D];
    __shared__ __align__(16) float rsh[NW][D];
    __shared__ float msh[NW], dsh[NW];

    int b  = blockIdx.x / SPLITS;
    int sp = blockIdx.x % SPLITS;
    int t = threadIdx.x;
    int w = t >> 5, lane = t & 31;

    int segs = g_segoff[b], sege = g_segoff[b + 1];
    int total = sege - segs;
    int start = segs + (int)(((long long)total * sp) / SPLITS);
    int end   = segs + (int)(((long long)total * (sp + 1)) / SPLITS);

    q_sh[t]       = g_qstar[b * QS + t];
    q_sh[t + 256] = g_qstar[b * QS + t + 256];
    __syncthreads();

    float qr[16];
    #pragma unroll
    for (int c = 0; c < 4; c++) {
        float4 qv = *(const float4*)&q_sh[c * 128 + lane * 4];
        qr[c * 4 + 0] = qv.x; qr[c * 4 + 1] = qv.y;
        qr[c * 4 + 2] = qv.z; qr[c * 4 + 3] = qv.w;
    }

    float m = -INFINITY, d = 0.0f;
    float r[16];
    #pragma unroll
    for (int j = 0; j < 16; j++) r[j] = 0.0f;

    int n = start + w;
    float4 xb0, xb1, xb2, xb3;
    if (n < end) {
        const float* p = x + (size_t)n * D;
        xb0 = ((const float4*)(p      ))[lane];
        xb1 = ((const float4*)(p + 128))[lane];
        xb2 = ((const float4*)(p + 256))[lane];
        xb3 = ((const float4*)(p + 384))[lane];
    }
    while (n < end) {
        float4 c0 = xb0, c1 = xb1, c2 = xb2, c3 = xb3;
        int nn = n + NW;
        if (nn < end) {
            const float* p = x + (size_t)nn * D;
            xb0 = ((const float4*)(p      ))[lane];
            xb1 = ((const float4*)(p + 128))[lane];
            xb2 = ((const float4*)(p + 256))[lane];
            xb3 = ((const float4*)(p + 384))[lane];
        }
        float s = c0.x * qr[0]  + c0.y * qr[1]  + c0.z * qr[2]  + c0.w * qr[3]
                + c1.x * qr[4]  + c1.y * qr[5]  + c1.z * qr[6]  + c1.w * qr[7]
                + c2.x * qr[8]  + c2.y * qr[9]  + c2.z * qr[10] + c2.w * qr[11]
                + c3.x * qr[12] + c3.y * qr[13] + c3.z * qr[14] + c3.w * qr[15];
        #pragma unroll
        for (int o = 16; o > 0; o >>= 1) s += __shfl_xor_sync(0xffffffffu, s, o);

        if (s > m) {
            float al = __expf(m - s);   // first iteration: exp(-inf) = 0
            d = d * al + 1.0f;
            r[0]  = r[0]  * al + c0.x;  r[1]  = r[1]  * al + c0.y;
            r[2]  = r[2]  * al + c0.z;  r[3]  = r[3]  * al + c0.w;
            r[4]  = r[4]  * al + c1.x;  r[5]  = r[5]  * al + c1.y;
            r[6]  = r[6]  * al + c1.z;  r[7]  = r[7]  * al + c1.w;
            r[8]  = r[8]  * al + c2.x;  r[9]  = r[9]  * al + c2.y;
            r[10] = r[10] * al + c2.z;  r[11] = r[11] * al + c2.w;
            r[12] = r[12] * al + c3.x;  r[13] = r[13] * al + c3.y;
            r[14] = r[14] * al + c3.z;  r[15] = r[15] * al + c3.w;
            m = s;
        } else {
            float wv = __expf(s - m);
            d += wv;
            r[0]  += wv * c0.x;  r[1]  += wv * c0.y;  r[2]  += wv * c0.z;  r[3]  += wv * c0.w;
            r[4]  += wv * c1.x;  r[5]  += wv * c1.y;  r[6]  += wv * c1.z;  r[7]  += wv * c1.w;
            r[8]  += wv * c2.x;  r[9]  += wv * c2.y;  r[10] += wv * c2.z;  r[11] += wv * c2.w;
            r[12] += wv * c3.x;  r[13] += wv * c3.y;  r[14] += wv * c3.z;  r[15] += wv * c3.w;
        }
        n = nn;
    }

    if (lane == 0) { msh[w] = m; dsh[w] = d; }
    #pragma unroll
    for (int c = 0; c < 4; c++)
        *(float4*)&rsh[w][c * 128 + lane * 4] =
            make_float4(r[c * 4], r[c * 4 + 1], r[c * 4 + 2], r[c * 4 + 3]);
    __syncthreads();

    float M = msh[0];
    #pragma unroll
    for (int p = 1; p < NW; p++) M = fmaxf(M, msh[p]);
    float Mg = isfinite(M) ? M : 0.0f;
    float dd = 0.0f, r0 = 0.0f, r1 = 0.0f;
    #pragma unroll
    for (int p = 0; p < NW; p++) {
        float sc = __expf(msh[p] - Mg);
        dd += dsh[p] * sc;
        r0 += rsh[p][t] * sc;
        r1 += rsh[p][t + 256] * sc;
    }
    int pid = b * SPLITS + sp;
    g_pr[(size_t)pid * D + t]       = r0;
    g_pr[(size_t)pid * D + t + 256] = r1;
    if (t == 0) { g_pm[pid] = M; g_pd[pid] = dd; }
}

// ---------------- combine split partials -> r in g_qstar ----------------
__global__ void k_attn_combine() {
    __shared__ float sm[SPLITS], sd[SPLITS];
    int b = blockIdx.x, t = threadIdx.x;
    if (t < SPLITS) {
        sm[t] = g_pm[b * SPLITS + t];
        sd[t] = g_pd[b * SPLITS + t];
    }
    __syncthreads();
    float M = -INFINITY;
    #pragma unroll
    for (int p = 0; p < SPLITS; p++) M = fmaxf(M, sm[p]);
    if (!isfinite(M)) M = 0.0f;
    float denom = 0.0f;
    float scale[SPLITS];
    #pragma unroll
    for (int p = 0; p < SPLITS; p++) {
        scale[p] = expf(sm[p] - M);
        denom += sd[p] * scale[p];
    }
    float inv = 1.0f / (denom + 1e-16f);
    float r0 = 0.0f, r1 = 0.0f;
    #pragma unroll
    for (int p = 0; p < SPLITS; p++) {
        const float* pr = g_pr + (size_t)(b * SPLITS + p) * D;
        r0 += pr[t]       * scale[p];
        r1 += pr[t + 256] * scale[p];
    }
    g_qstar[b * QS + D + t]       = r0 * inv;
    g_qstar[b * QS + D + t + 256] = r1 * inv;
}

// ---------------- projection ----------------
__global__ void k_proj(const float* __restrict__ Wp, const float* __restrict__ bp,
                       float* __restrict__ out) {
    int gw = (blockIdx.x * 256 + threadIdx.x) >> 5;
    int lane = threadIdx.x & 31;
    int bb = gw >> 8, o = gw & 255;
    const float* qr = g_qstar + bb * QS;
    const float* wr = Wp + o * QS;
    float s = 0.0f;
    #pragma unroll
    for (int it = 0; it < QS / 128; it++) {
        int k = lane * 4 + it * 128;
        float4 a = *(const float4*)(qr + k);
        float4 w = *(const float4*)(wr + k);
        s += a.x * w.x + a.y * w.y + a.z * w.z + a.w * w.w;
    }
    #pragma unroll
    for (int off = 16; off > 0; off >>= 1) s += __shfl_xor_sync(0xffffffffu, s, off);
    if (lane == 0) out[gw] = s + bp[o];
}

// ---------------- launch ----------------
extern "C" void kernel_launch(void* const* d_in, const int* in_sizes, int n_in,
                              void* d_out, int out_size) {
    const float* x      = (const float*)d_in[0];
    const void*  batch  = d_in[1];
    const float* W_ih   = (const float*)d_in[2];
    const float* W_hh   = (const float*)d_in[3];
    const float* b_ih   = (const float*)d_in[4];
    const float* b_hh   = (const float*)d_in[5];
    const float* W_proj = (const float*)d_in[6];
    const float* b_proj = (const float*)d_in[7];
    (void)n_in; (void)out_size;
    int N = in_sizes[1];

    int init_blocks = WCOMB_BLKS + STEP0_BLKS + (N + 255) / 256;
    k_init<<<init_blocks, 256>>>(batch, N, W_ih, W_hh, b_ih, b_hh);

    k_attn_part<<<B * SPLITS, 256>>>(x);
    k_attn_combine<<<B, 256>>>();

    for (int s = 1; s < 3; s++) {
        k_gemm_tc<<<dim3(FOURD / GBN, B / GBM), 256>>>();
        k_lstm_ew<<<(B * D / 4 + 127) / 128, 128>>>();
        k_attn_part<<<B * SPLITS, 256>>>(x);
        k_attn_combine<<<B, 256>>>();
    }

    k_proj<<<(B * 256) / 8, 256>>>(W_proj, b_proj, (float*)d_out);
}